// round 4
// baseline (speedup 1.0000x reference)
#include <cuda_runtime.h>

#define NB 512
#define NT 1024
#define NK 48
#define SSTART 46
#define SEND 47
#define NEGV (-10000.0f)
#define L2E 1.4426950408889634f
#define LN2F 0.6931471805599453f

// per-batch smem block layout (bytes)
#define OFF_E   (NT*NK)            // 49152: bp u8[NT*NK] below
#define OFF_V   (OFF_E + 2*NK*4)
#define OFF_S0  (OFF_V + 2*NK*4)
#define OFF_RED (OFF_S0 + 16)
#define SLOT    (((OFF_RED + 2*NK*4) + 127) & ~127)   // padded per-batch stride
#define SMEM_BYTES (2*SLOT)

__device__ __forceinline__ float ex2f(float x){ float y; asm("ex2.approx.ftz.f32 %0, %1;":"=f"(y):"f"(x)); return y; }
__device__ __forceinline__ float lg2f(float x){ float y; asm("lg2.approx.f32 %0, %1;":"=f"(y):"f"(x)); return y; }
__device__ __forceinline__ unsigned long long ffma2(unsigned long long a, unsigned long long b, unsigned long long c){
    unsigned long long d; asm("fma.rn.f32x2 %0, %1, %2, %3;" : "=l"(d) : "l"(a), "l"(b), "l"(c)); return d;
}
__device__ __forceinline__ unsigned long long fadd2(unsigned long long a, unsigned long long b){
    unsigned long long d; asm("add.rn.f32x2 %0, %1, %2;" : "=l"(d) : "l"(a), "l"(b)); return d;
}
__device__ __forceinline__ unsigned long long pk2(float lo, float hi){
    unsigned long long d; asm("mov.b64 %0, {%1, %2};" : "=l"(d) : "f"(lo), "f"(hi)); return d;
}
__device__ __forceinline__ void upk2(unsigned long long v, float& lo, float& hi){
    asm("mov.b64 {%0, %1}, %2;" : "=f"(lo), "=f"(hi) : "l"(v));
}
#define BSYNC() asm volatile("bar.sync %0, 128;" :: "r"(1 + batch) : "memory")

__global__ __launch_bounds__(256, 2)
void crf_kernel(const float* __restrict__ feats,
                const float* __restrict__ trans,
                float* __restrict__ out)
{
    extern __shared__ char smc[];
    const int tid   = threadIdx.x;
    const int batch = tid >> 7;            // 0/1: which batch this thread serves
    const int bt    = tid & 127;           // thread id within batch group
    char* sb = smc + batch * SLOT;

    unsigned char* bp = (unsigned char*)sb;
    float* eB  = (float*)(sb + OFF_E);     // exp2 of normalized log2-alpha, dbl-buffered
    float* vB  = (float*)(sb + OFF_V);     // viterbi values (plain), dbl-buffered
    float* s0B = (float*)(sb + OFF_S0);    // broadcast normalized A[0] (shift)
    float* red = (float*)(sb + OFF_RED);   // final reduction terms

    const int b = blockIdx.x * 2 + batch;
    const bool isF = (bt < 64);            // per batch: warps 0-1 forward, 2-3 viterbi
    const int j = isF ? bt : (bt - 64);
    const bool act = (j < NK);
    const float* f = feats + (size_t)b * NT * NK;

    // fwd: packed exp2(trans*log2e) row;  vit: packed plain trans row
    unsigned long long tp[NK/2];
    float A = 0.f, Csum = 0.f, vj = 0.f, featv = 0.f;

    if (act) {
        #pragma unroll
        for (int c = 0; c < NK/2; ++c) {
            float t0 = trans[j*NK + 2*c];
            float t1 = trans[j*NK + 2*c + 1];
            if (j == SSTART)   { t0 = NEGV; t1 = NEGV; }   // no transition into START row
            if (2*c   == SEND)   t0 = NEGV;                // no transition out of END col
            if (2*c+1 == SEND)   t1 = NEGV;
            if (isF) tp[c] = pk2(ex2f(t0 * L2E), ex2f(t1 * L2E));  // masked -> exact 0
            else     tp[c] = pk2(t0, t1);
        }
        if (isF) {
            A = (j == SSTART) ? 0.f : NEGV * L2E;
            eB[j] = (j == SSTART) ? 1.f : 0.f;
        } else {
            vj = (j == SSTART) ? 0.f : NEGV;
            vB[j] = vj;
        }
        featv = __ldg(f + j);
    }
    if (bt == 0) s0B[0] = 0.f;
    BSYNC();

    int cur = 0;
    #pragma unroll 1
    for (int t = 0; t < NT; ++t) {
        const int nxt = cur ^ 1;
        float featn = 0.f;
        if (act && t + 1 < NT) featn = __ldg(f + (t+1)*NK + j);   // prefetch

        if (act) {
            if (isF) {
                // forward: s_j = sum_p E[j][p]*e[p]  (24 packed f32x2 FFMA)
                const ulonglong2* e2p = (const ulonglong2*)(eB + cur*NK);
                unsigned long long acc0 = 0ull, acc1 = 0ull;
                #pragma unroll
                for (int c = 0; c < NK/4; ++c) {
                    ulonglong2 ev = e2p[c];                       // broadcast LDS.128
                    acc0 = ffma2(tp[2*c    ], ev.x, acc0);
                    acc1 = ffma2(tp[2*c + 1], ev.y, acc1);
                }
                float a0l,a0h,a1l,a1h;
                upk2(acc0, a0l, a0h); upk2(acc1, a1l, a1h);
                float s = (a0l + a0h) + (a1l + a1h);
                float d = s0B[cur];                  // prev step's NORMALIZED A[0]
                d = fminf(fmaxf(d, -200.f), 200.f);  // defensive; algebra stays exact
                float raw = lg2f(s) + featv * L2E;
                Csum += d;
                A = raw - d;
                eB[nxt*NK + j] = ex2f(A);
                if (j == 0) s0B[nxt] = A;
            } else {
                // viterbi: plain float, identical op order to reference -> bit-exact
                const ulonglong2* v2p = (const ulonglong2*)(vB + cur*NK);
                float m0=-3.4e38f, m1=-3.4e38f, m2=-3.4e38f, m3=-3.4e38f;
                int   i0=0, i1=1, i2=2, i3=3;
                #pragma unroll
                for (int c = 0; c < NK/4; ++c) {
                    ulonglong2 vv = v2p[c];                       // broadcast LDS.128
                    unsigned long long y01 = fadd2(vv.x, tp[2*c]);     // 2 IEEE RN adds
                    unsigned long long y23 = fadd2(vv.y, tp[2*c+1]);
                    float y0,y1,y2,y3;
                    upk2(y01, y0, y1); upk2(y23, y2, y3);
                    if (y0 > m0) { m0=y0; i0=4*c+0; }
                    if (y1 > m1) { m1=y1; i1=4*c+1; }
                    if (y2 > m2) { m2=y2; i2=4*c+2; }
                    if (y3 > m3) { m3=y3; i3=4*c+3; }
                }
                // merge with first-max tie-break (matches jnp.argmax)
                float bm = m0; int bi = i0;
                if (m1 > bm || (m1 == bm && i1 < bi)) { bm=m1; bi=i1; }
                if (m2 > bm || (m2 == bm && i2 < bi)) { bm=m2; bi=i2; }
                if (m3 > bm || (m3 == bm && i3 < bi)) { bm=m3; bi=i3; }
                vj = bm + featv;                     // emission added AFTER max (reference)
                bp[t*NK + j] = (unsigned char)bi;
                vB[nxt*NK + j] = vj;
            }
        }
        featv = featn;
        cur = nxt;
        BSYNC();
    }

    // ---- termination ----
    if (act) {
        float te = trans[SEND*NK + j];
        if (j == SEND) te = NEGV;                    // column END masked
        if (isF) red[j]      = A  + te * L2E;        // log2 domain (C added at end)
        else     red[NK + j] = vj + te;              // plain, bit-exact
    }
    BSYNC();

    if (bt == 0) {
        // logz = logsumexp(alpha + trans[END])
        float m = -3.4e38f;
        #pragma unroll
        for (int p = 0; p < NK; ++p) m = fmaxf(m, red[p]);
        float s = 0.f;
        #pragma unroll
        for (int p = 0; p < NK; ++p) s += ex2f(red[p] - m);
        out[b] = (m + lg2f(s) + Csum) * LN2F;
    }
    if (bt == 64) {
        // terminal first-max argmax + smem backtrace (concurrent with logz thread)
        float bm = -3.4e38f; int last = 0;
        #pragma unroll
        for (int p = 0; p < NK; ++p) {
            float y = red[NK + p];
            if (y > bm) { bm = y; last = p; }
        }
        out[NB + b] = bm;
        float* po = out + 2*NB + (size_t)b * NT;
        int tag = last;
        #pragma unroll 1
        for (int t = NT - 1; t >= 0; --t) {
            po[t] = (float)tag;
            tag = bp[t*NK + tag];
        }
    }
}

extern "C" void kernel_launch(void* const* d_in, const int* in_sizes, int n_in,
                              void* d_out, int out_size)
{
    const float* feats = (const float*)d_in[0];
    const float* trans = (const float*)d_in[1];
    float* out = (float*)d_out;
    cudaFuncSetAttribute(crf_kernel, cudaFuncAttributeMaxDynamicSharedMemorySize,
                         SMEM_BYTES);
    crf_kernel<<<NB/2, 256, SMEM_BYTES>>>(feats, trans, out);
}

// round 5
// speedup vs baseline: 1.5020x; 1.5020x over previous
#include <cuda_runtime.h>

#define NB 512
#define NT 1024
#define NK 48
#define SSTART 46
#define SEND 47
#define NEGV (-10000.0f)
#define L2E 1.4426950408889634f
#define LN2F 0.6931471805599453f

// dyn smem: bp[NT*NK] u8 | e[2][NK] f32 | v[2][NK] f32 | s0[2] | red[2*NK]
#define OFF_E   (NT*NK)
#define OFF_V   (OFF_E + 2*NK*4)
#define OFF_S0  (OFF_V + 2*NK*4)
#define OFF_RED (OFF_S0 + 16)
#define SMEM_BYTES (OFF_RED + 2*NK*4)

#define PD 4   // feats prefetch pipeline depth (steps)

__device__ __forceinline__ float ex2f(float x){ float y; asm("ex2.approx.ftz.f32 %0, %1;":"=f"(y):"f"(x)); return y; }
__device__ __forceinline__ float lg2f(float x){ float y; asm("lg2.approx.f32 %0, %1;":"=f"(y):"f"(x)); return y; }
__device__ __forceinline__ unsigned long long ffma2(unsigned long long a, unsigned long long b, unsigned long long c){
    unsigned long long d; asm("fma.rn.f32x2 %0, %1, %2, %3;" : "=l"(d) : "l"(a), "l"(b), "l"(c)); return d;
}
__device__ __forceinline__ unsigned long long fadd2(unsigned long long a, unsigned long long b){
    unsigned long long d; asm("add.rn.f32x2 %0, %1, %2;" : "=l"(d) : "l"(a), "l"(b)); return d;
}
__device__ __forceinline__ unsigned long long pk2(float lo, float hi){
    unsigned long long d; asm("mov.b64 %0, {%1, %2};" : "=l"(d) : "f"(lo), "f"(hi)); return d;
}
__device__ __forceinline__ void upk2(unsigned long long v, float& lo, float& hi){
    asm("mov.b64 {%0, %1}, %2;" : "=f"(lo), "=f"(hi) : "l"(v));
}

__global__ __launch_bounds__(128, 4)
void crf_kernel(const float* __restrict__ feats,
                const float* __restrict__ trans,
                float* __restrict__ out)
{
    extern __shared__ char smc[];
    unsigned char* bp = (unsigned char*)smc;
    float* eB  = (float*)(smc + OFF_E);    // exp2 of normalized log2-alpha, dbl-buffered
    float* vB  = (float*)(smc + OFF_V);    // viterbi values (plain), dbl-buffered
    float* s0B = (float*)(smc + OFF_S0);   // broadcast normalized A[0] (shift)
    float* red = (float*)(smc + OFF_RED);  // final reduction terms

    const int b   = blockIdx.x;
    const int tid = threadIdx.x;
    const bool isF = (tid < 64);           // warps 0-1: forward; warps 2-3: viterbi
    const int j   = isF ? tid : (tid - 64);
    const bool act = (j < NK);
    const float* f = feats + (size_t)b * NT * NK;

    // fwd: packed exp2(trans*log2e) row;  vit: packed plain trans row
    unsigned long long tp[NK/2];
    float A = 0.f, Csum = 0.f, vj = 0.f;

    if (act) {
        #pragma unroll
        for (int c = 0; c < NK/2; ++c) {
            float t0 = trans[j*NK + 2*c];
            float t1 = trans[j*NK + 2*c + 1];
            if (j == SSTART)   { t0 = NEGV; t1 = NEGV; }   // no transition into START row
            if (2*c   == SEND)   t0 = NEGV;                // no transition out of END col
            if (2*c+1 == SEND)   t1 = NEGV;
            if (isF) tp[c] = pk2(ex2f(t0 * L2E), ex2f(t1 * L2E));  // masked -> exact 0
            else     tp[c] = pk2(t0, t1);
        }
        if (isF) {
            A = (j == SSTART) ? 0.f : NEGV * L2E;
            eB[j] = (j == SSTART) ? 1.f : 0.f;
        } else {
            vj = (j == SSTART) ? 0.f : NEGV;
            vB[j] = vj;
        }
    }
    // feats register pipeline, depth PD (covers DRAM latency across PD steps)
    float fq[PD];
    if (act) {
        #pragma unroll
        for (int i = 0; i < PD; ++i) fq[i] = __ldg(f + i*NK + j);
    }
    if (tid == 0) s0B[0] = 0.f;
    __syncthreads();

    #pragma unroll 1
    for (int g = 0; g < NT/PD; ++g) {
        #pragma unroll
        for (int u = 0; u < PD; ++u) {
            const int t  = g*PD + u;
            const int cb = u & 1;            // buffer parity (t even -> 0)
            const int nb = cb ^ 1;
            if (act) {
                const float featv = fq[u];                 // loaded PD steps ago
                float nf = 0.f;
                if (t + PD < NT) nf = __ldg(f + (t+PD)*NK + j);   // deep prefetch
                if (isF) {
                    // forward: s_j = sum_p E[j][p]*e[p]  (24 packed f32x2 FFMA)
                    const ulonglong2* e2p = (const ulonglong2*)(eB + cb*NK);
                    unsigned long long acc0 = 0ull, acc1 = 0ull;
                    #pragma unroll
                    for (int c = 0; c < NK/4; ++c) {
                        ulonglong2 ev = e2p[c];            // broadcast LDS.128
                        acc0 = ffma2(tp[2*c    ], ev.x, acc0);
                        acc1 = ffma2(tp[2*c + 1], ev.y, acc1);
                    }
                    float a0l,a0h,a1l,a1h;
                    upk2(acc0, a0l, a0h); upk2(acc1, a1l, a1h);
                    float s = (a0l + a0h) + (a1l + a1h);
                    float d = s0B[cb];                     // prev step's NORMALIZED A[0]
                    d = fminf(fmaxf(d, -200.f), 200.f);    // defensive; algebra exact
                    float raw = lg2f(s) + featv * L2E;
                    Csum += d;
                    A = raw - d;
                    eB[nb*NK + j] = ex2f(A);
                    if (j == 0) s0B[nb] = A;
                } else {
                    // viterbi: plain float, identical op order to reference -> bit-exact
                    const ulonglong2* v2p = (const ulonglong2*)(vB + cb*NK);
                    float m0=-3.4e38f, m1=-3.4e38f, m2=-3.4e38f, m3=-3.4e38f;
                    int   i0=0, i1=1, i2=2, i3=3;
                    #pragma unroll
                    for (int c = 0; c < NK/4; ++c) {
                        ulonglong2 vv = v2p[c];            // broadcast LDS.128
                        unsigned long long y01 = fadd2(vv.x, tp[2*c]);   // 2 IEEE RN adds
                        unsigned long long y23 = fadd2(vv.y, tp[2*c+1]);
                        float y0,y1,y2,y3;
                        upk2(y01, y0, y1); upk2(y23, y2, y3);
                        if (y0 > m0) { m0=y0; i0=4*c+0; }
                        if (y1 > m1) { m1=y1; i1=4*c+1; }
                        if (y2 > m2) { m2=y2; i2=4*c+2; }
                        if (y3 > m3) { m3=y3; i3=4*c+3; }
                    }
                    // merge with first-max tie-break (matches jnp.argmax)
                    float bm = m0; int bi = i0;
                    if (m1 > bm || (m1 == bm && i1 < bi)) { bm=m1; bi=i1; }
                    if (m2 > bm || (m2 == bm && i2 < bi)) { bm=m2; bi=i2; }
                    if (m3 > bm || (m3 == bm && i3 < bi)) { bm=m3; bi=i3; }
                    vj = bm + featv;                       // emission added AFTER max
                    bp[t*NK + j] = (unsigned char)bi;
                    vB[nb*NK + j] = vj;
                }
                fq[u] = nf;
            }
            __syncthreads();
        }
    }

    // ---- termination ----
    if (act) {
        float te = trans[SEND*NK + j];
        if (j == SEND) te = NEGV;                    // column END masked
        if (isF) red[j]      = A  + te * L2E;        // log2 domain (C added at end)
        else     red[NK + j] = vj + te;              // plain, bit-exact
    }
    __syncthreads();

    if (tid == 0) {
        // logz = logsumexp(alpha + trans[END])
        float m = -3.4e38f;
        #pragma unroll
        for (int p = 0; p < NK; ++p) m = fmaxf(m, red[p]);
        float s = 0.f;
        #pragma unroll
        for (int p = 0; p < NK; ++p) s += ex2f(red[p] - m);
        out[b] = (m + lg2f(s) + Csum) * LN2F;
    }
    if (tid == 64) {
        // terminal first-max argmax + smem backtrace (concurrent with logz thread)
        float bm = -3.4e38f; int last = 0;
        #pragma unroll
        for (int p = 0; p < NK; ++p) {
            float y = red[NK + p];
            if (y > bm) { bm = y; last = p; }
        }
        out[NB + b] = bm;
        float* po = out + 2*NB + (size_t)b * NT;
        int tag = last;
        #pragma unroll 1
        for (int t = NT - 1; t >= 0; --t) {
            po[t] = (float)tag;
            tag = bp[t*NK + tag];
        }
    }
}

extern "C" void kernel_launch(void* const* d_in, const int* in_sizes, int n_in,
                              void* d_out, int out_size)
{
    const float* feats = (const float*)d_in[0];
    const float* trans = (const float*)d_in[1];
    float* out = (float*)d_out;
    cudaFuncSetAttribute(crf_kernel, cudaFuncAttributeMaxDynamicSharedMemorySize,
                         SMEM_BYTES);
    crf_kernel<<<NB, 128, SMEM_BYTES>>>(feats, trans, out);
}